// round 1
// baseline (speedup 1.0000x reference)
#include <cuda_runtime.h>
#include <cuda_bf16.h>

// Problem shape (fixed by the reference setup_inputs):
//   x: (B=32, L=4096, N=256) float32, missing entries are NaN.
//   forward-fill along L per (b, n); 0.0 before first observation.
// Output: x_filled (and, if out_size indicates, mask as 1.0/0.0 floats).

#define BB 32
#define LL 4096
#define NN 256
#define CC 64            // number of L-chunks
#define LC (LL / CC)     // 64 steps per chunk
#define N4 (NN / 4)      // 64 float4 groups per step

// Scratch: per-(b, chunk, n) carry values. 32*64*256 floats = 2 MB each.
__device__ float g_chunk_last[BB * CC * NN];
__device__ float g_carry_in[BB * CC * NN];

static __device__ __forceinline__ float sel_obs(float v, float r) {
    // observed iff not NaN (mask == ~isnan(x) by construction)
    return (v == v) ? v : r;
}

// Kernel 1: per (b, chunk, n4), find last observed value inside the chunk.
// NaN sentinel means "no observation in this chunk".
__global__ void __launch_bounds__(256) k_chunk_scan(const float4* __restrict__ x) {
    int t = blockIdx.x * blockDim.x + threadIdx.x;       // over B*C*N4 = 131072
    int n4 = t % N4;
    int c  = (t / N4) % CC;
    int b  = t / (N4 * CC);

    float nanf_ = __int_as_float(0x7fc00000);
    float4 run = make_float4(nanf_, nanf_, nanf_, nanf_);

    const float4* xp = x + ((size_t)(b * LL + c * LC) * N4 + n4);
    #pragma unroll 8
    for (int l = 0; l < LC; l++) {
        float4 v = xp[(size_t)l * N4];
        run.x = sel_obs(v.x, run.x);
        run.y = sel_obs(v.y, run.y);
        run.z = sel_obs(v.z, run.z);
        run.w = sel_obs(v.w, run.w);
    }
    reinterpret_cast<float4*>(g_chunk_last)[(b * CC + c) * N4 + n4] = run;
}

// Kernel 2: per (b, n4), sequential prefix over the CC chunk carries.
// carry_in[chunk c] = value to forward-fill with at the start of chunk c.
// Chunk 0 is seeded with 0.0 (fill value before the first observation).
__global__ void __launch_bounds__(256) k_carry(void) {
    int t = blockIdx.x * blockDim.x + threadIdx.x;       // over B*N4 = 2048
    int n4 = t % N4;
    int b  = t / N4;

    float4 pref = make_float4(0.f, 0.f, 0.f, 0.f);
    for (int c = 0; c < CC; c++) {
        int idx = (b * CC + c) * N4 + n4;
        reinterpret_cast<float4*>(g_carry_in)[idx] = pref;
        float4 cl = reinterpret_cast<const float4*>(g_chunk_last)[idx];
        pref.x = sel_obs(cl.x, pref.x);
        pref.y = sel_obs(cl.y, pref.y);
        pref.z = sel_obs(cl.z, pref.z);
        pref.w = sel_obs(cl.w, pref.w);
    }
}

// Kernel 3: per (b, chunk, n4), re-scan the chunk from its carry-in and
// write the filled values (and optionally the mask as 1.0/0.0 floats).
template <bool WRITE_MASK>
__global__ void __launch_bounds__(256) k_fill(const float4* __restrict__ x,
                                              float4* __restrict__ out,
                                              float4* __restrict__ outm) {
    int t = blockIdx.x * blockDim.x + threadIdx.x;       // over B*C*N4
    int n4 = t % N4;
    int c  = (t / N4) % CC;
    int b  = t / (N4 * CC);

    float4 run = reinterpret_cast<const float4*>(g_carry_in)[(b * CC + c) * N4 + n4];

    size_t base = (size_t)(b * LL + c * LC) * N4 + n4;
    const float4* xp = x + base;
    float4* op = out + base;
    #pragma unroll 8
    for (int l = 0; l < LC; l++) {
        float4 v = xp[(size_t)l * N4];
        run.x = sel_obs(v.x, run.x);
        run.y = sel_obs(v.y, run.y);
        run.z = sel_obs(v.z, run.z);
        run.w = sel_obs(v.w, run.w);
        op[(size_t)l * N4] = run;
        if (WRITE_MASK) {
            float4 m;
            m.x = (v.x == v.x) ? 1.0f : 0.0f;
            m.y = (v.y == v.y) ? 1.0f : 0.0f;
            m.z = (v.z == v.z) ? 1.0f : 0.0f;
            m.w = (v.w == v.w) ? 1.0f : 0.0f;
            outm[base + (size_t)l * N4] = m;
        }
    }
}

extern "C" void kernel_launch(void* const* d_in, const int* in_sizes, int n_in,
                              void* d_out, int out_size) {
    const float4* x = (const float4*)d_in[0];
    long long total = (long long)in_sizes[0];            // B*L*N = 33554432
    float* out = (float*)d_out;

    int work = BB * CC * N4;                              // 131072
    int blocks = work / 256;                              // 512

    k_chunk_scan<<<blocks, 256>>>(x);
    k_carry<<<(BB * N4) / 256, 256>>>();

    if ((long long)out_size >= 2 * total) {
        // second half of d_out: mask as float 1.0/0.0
        k_fill<true><<<blocks, 256>>>(x, (float4*)out,
                                      (float4*)(out + total));
    } else {
        k_fill<false><<<blocks, 256>>>(x, (float4*)out, nullptr);
    }
}

// round 3
// speedup vs baseline: 1.6844x; 1.6844x over previous
#include <cuda_runtime.h>
#include <cuda_bf16.h>

// Forward-fill (LOCF) over x:(B=32, L=4096, N=256) fp32, NaN = missing.
// Single-pass chunked scan with decoupled lookback (aggregate-only).
//
//   chunk = 32 timesteps; grid = B * (L/32) = 4096 CTAs, 256 threads.
//   thread = one channel n; its 32-step column lives in registers.
//   publish: 64-bit word {status(hi32)=1, aggregate(lo32)} per (chunk, n).
//   carry: walk back over predecessors' aggregates until non-NaN (len~1),
//          or 0.0 if we fall off the front of this batch.

#define BB 32
#define LL 4096
#define NN 256
#define LC 32
#define CC (LL / LC)          // 128 chunks per batch
#define NCHUNK (BB * CC)      // 4096 CTAs
#define NPUB (NCHUNK * NN)    // 1M entries * 8B = 8 MB

__device__ unsigned long long g_pub[NPUB];

static __device__ __forceinline__ unsigned long long ld_cg_u64(const unsigned long long* p) {
    unsigned long long v;
    asm volatile("ld.global.cg.u64 %0, [%1];" : "=l"(v) : "l"(p) : "memory");
    return v;
}
static __device__ __forceinline__ void st_cg_u64(unsigned long long* p, unsigned long long v) {
    asm volatile("st.global.cg.u64 [%0], %1;" :: "l"(p), "l"(v) : "memory");
}

__global__ void __launch_bounds__(256) k_clear(void) {
    int t = blockIdx.x * blockDim.x + threadIdx.x;
    // 4 entries per thread: 1M / (256*1024) = 4
    ulonglong2* p = reinterpret_cast<ulonglong2*>(g_pub);
    p[2 * t + 0] = make_ulonglong2(0ull, 0ull);
    p[2 * t + 1] = make_ulonglong2(0ull, 0ull);
}

template <bool WRITE_MASK>
__global__ void __launch_bounds__(256) k_locf(const float* __restrict__ x,
                                              float* __restrict__ out,
                                              float* __restrict__ outm) {
    const int n   = threadIdx.x;          // channel
    const int bid = blockIdx.x;           // (b, c)
    const int c   = bid % CC;
    const int b   = bid / CC;

    const size_t base = ((size_t)b * LL + (size_t)c * LC) * NN + n;

    // ---- load 32-step column into registers (coalesced: warp reads 128B per l)
    float v[LC];
    #pragma unroll
    for (int l = 0; l < LC; l++)
        v[l] = __ldcs(x + base + (size_t)l * NN);

    // ---- in-chunk aggregate: last observed value, NaN if none
    float agg = __int_as_float(0x7fc00000);
    #pragma unroll
    for (int l = 0; l < LC; l++)
        agg = (v[l] == v[l]) ? v[l] : agg;

    // ---- publish {status=1, agg} as one atomic 64-bit store
    unsigned long long w = (1ull << 32) | (unsigned long long)__float_as_uint(agg);
    st_cg_u64(&g_pub[(size_t)bid * NN + n], w);

    // ---- lookback: carry-in = nearest earlier non-NaN aggregate, else 0.0
    float carry = 0.0f;
    if (c > 0) {
        int p = bid - 1;
        const int pmin = b * CC;          // first chunk bid of this batch
        while (p >= pmin) {
            unsigned long long pw = ld_cg_u64(&g_pub[(size_t)p * NN + n]);
            while ((pw >> 32) == 0) {
                __nanosleep(40);
                pw = ld_cg_u64(&g_pub[(size_t)p * NN + n]);
            }
            float pa = __uint_as_float((unsigned int)pw);
            if (pa == pa) { carry = pa; break; }   // found an observation
            p--;                                   // empty chunk (~never): keep walking
        }
    }

    // ---- replay with carry, write filled values (coalesced scalar stores)
    float run = carry;
    #pragma unroll
    for (int l = 0; l < LC; l++) {
        run = (v[l] == v[l]) ? v[l] : run;
        __stcs(out + base + (size_t)l * NN, run);
        if (WRITE_MASK)
            __stcs(outm + base + (size_t)l * NN, (v[l] == v[l]) ? 1.0f : 0.0f);
    }
}

extern "C" void kernel_launch(void* const* d_in, const int* in_sizes, int n_in,
                              void* d_out, int out_size) {
    const float* x = (const float*)d_in[0];
    long long total = (long long)in_sizes[0];   // 33554432
    float* out = (float*)d_out;

    k_clear<<<NPUB / (256 * 4), 256>>>();

    if ((long long)out_size >= 2 * total) {
        k_locf<true><<<NCHUNK, 256>>>(x, out, out + total);
    } else {
        k_locf<false><<<NCHUNK, 256>>>(x, out, nullptr);
    }
}